// round 9
// baseline (speedup 1.0000x reference)
#include <cuda_runtime.h>
#include <cstdint>

#define B_ROWS 16384
#define NCLASS 1000
#define DIM 1024
#define ROW_BYTES (DIM * 4)                 // 4096 B per row
#define WARPS_PER_BLOCK 8
#define THREADS (WARPS_PER_BLOCK * 32)
#define NBLOCKS (B_ROWS / WARPS_PER_BLOCK)  // 2048

// Dynamic SMEM layout
#define SMEM_MBAR_OFF 0
#define SMEM_X_OFF    128
#define SMEM_C_OFF    (SMEM_X_OFF + WARPS_PER_BLOCK * ROW_BYTES)   // 128 + 32768
#define SMEM_TOTAL    (SMEM_C_OFF + WARPS_PER_BLOCK * ROW_BYTES)   // 65664

__device__ float g_partials[NBLOCKS];
__device__ unsigned int g_count;   // zero at load; reset each run -> graph-replay safe

__device__ __forceinline__ uint32_t s2u(const void* p) {
    uint32_t a;
    asm("{ .reg .u64 t; cvta.to.shared.u64 t, %1; cvt.u32.u64 %0, t; }"
        : "=r"(a) : "l"(p));
    return a;
}
__device__ __forceinline__ void mbar_init(uint32_t m, uint32_t cnt) {
    asm volatile("mbarrier.init.shared.b64 [%0], %1;" :: "r"(m), "r"(cnt) : "memory");
}
__device__ __forceinline__ void mbar_expect_tx(uint32_t m, uint32_t bytes) {
    asm volatile("mbarrier.arrive.expect_tx.shared.b64 _, [%0], %1;"
                 :: "r"(m), "r"(bytes) : "memory");
}
__device__ __forceinline__ void bulk_g2s(uint32_t dst, const void* src,
                                         uint32_t bytes, uint32_t m) {
    asm volatile(
        "cp.async.bulk.shared::cta.global.mbarrier::complete_tx::bytes "
        "[%0], [%1], %2, [%3];"
        :: "r"(dst), "l"(src), "r"(bytes), "r"(m) : "memory");
}
__device__ __forceinline__ void mbar_wait_parity(uint32_t m, uint32_t parity) {
    asm volatile(
        "{\n\t"
        ".reg .pred P;\n\t"
        "W_%=: mbarrier.try_wait.parity.acquire.cta.shared::cta.b64 P, [%0], %1, 0x989680;\n\t"
        "@P bra D_%=;\n\t"
        "bra W_%=;\n\t"
        "D_%=:\n\t"
        "}"
        :: "r"(m), "r"(parity) : "memory");
}

// 8 rows per block. x slab + 8 gathered center rows staged via cp.async.bulk
// (register-free, unbounded MLP). One warp per row computes from SMEM.
__global__ __launch_bounds__(THREADS) void proximity_fused_kernel(
    const float* __restrict__ x,
    const int* __restrict__ labels,
    const float* __restrict__ centers,
    float* __restrict__ out)
{
    extern __shared__ char smem[];
    const uint32_t sbase = s2u(smem);
    const uint32_t mbar  = sbase + SMEM_MBAR_OFF;

    const int warp = threadIdx.x >> 5;
    const int lane = threadIdx.x & 31;

    if (threadIdx.x == 0) mbar_init(mbar, 1);
    __syncthreads();

    if (threadIdx.x == 0) {
        // Load this block's 8 labels (two int4 = 32B, aligned).
        const int4* lp = reinterpret_cast<const int4*>(labels + blockIdx.x * WARPS_PER_BLOCK);
        int4 l0 = lp[0], l1 = lp[1];
        int labs[8] = { l0.x, l0.y, l0.z, l0.w, l1.x, l1.y, l1.z, l1.w };

        mbar_expect_tx(mbar, 2u * WARPS_PER_BLOCK * ROW_BYTES);  // 65536

        // x slab: 8 contiguous rows = 32 KB, one bulk copy.
        bulk_g2s(sbase + SMEM_X_OFF,
                 x + (size_t)blockIdx.x * WARPS_PER_BLOCK * DIM,
                 WARPS_PER_BLOCK * ROW_BYTES, mbar);

        // 8 gathered center rows, 4 KB each.
        #pragma unroll
        for (int i = 0; i < WARPS_PER_BLOCK; ++i) {
            int lab = min(max(labs[i], 0), NCLASS - 1);
            bulk_g2s(sbase + SMEM_C_OFF + i * ROW_BYTES,
                     centers + (size_t)lab * DIM,
                     ROW_BYTES, mbar);
        }
    }

    mbar_wait_parity(mbar, 0);

    // Compute from SMEM: warp w handles row w. LDS.128, conflict-free.
    const float4* __restrict__ xs =
        reinterpret_cast<const float4*>(smem + SMEM_X_OFF + warp * ROW_BYTES);
    const float4* __restrict__ cs =
        reinterpret_cast<const float4*>(smem + SMEM_C_OFF + warp * ROW_BYTES);

    float sxx = 0.f, scc = 0.f, sxc = 0.f;
    #pragma unroll
    for (int i = 0; i < 8; ++i) {
        float4 xv = xs[lane + 32 * i];
        float4 cv = cs[lane + 32 * i];
        sxx = fmaf(xv.x, xv.x, sxx);
        sxx = fmaf(xv.y, xv.y, sxx);
        sxx = fmaf(xv.z, xv.z, sxx);
        sxx = fmaf(xv.w, xv.w, sxx);
        scc = fmaf(cv.x, cv.x, scc);
        scc = fmaf(cv.y, cv.y, scc);
        scc = fmaf(cv.z, cv.z, scc);
        scc = fmaf(cv.w, cv.w, scc);
        sxc = fmaf(xv.x, cv.x, sxc);
        sxc = fmaf(xv.y, cv.y, sxc);
        sxc = fmaf(xv.z, cv.z, sxc);
        sxc = fmaf(xv.w, cv.w, sxc);
    }

    #pragma unroll
    for (int off = 16; off > 0; off >>= 1) {
        sxx += __shfl_down_sync(0xFFFFFFFFu, sxx, off);
        scc += __shfl_down_sync(0xFFFFFFFFu, scc, off);
        sxc += __shfl_down_sync(0xFFFFFFFFu, sxc, off);
    }

    __shared__ float s_dist[WARPS_PER_BLOCK];
    if (lane == 0) {
        const float eps = 1e-12f;
        float nx = fmaxf(sqrtf(sxx), eps);
        float nc = fmaxf(sqrtf(scc), eps);
        float d = sxx / (nx * nx) + scc / (nc * nc) - 2.0f * sxc / (nx * nc);
        d = fminf(fmaxf(d, 1e-12f), 1e12f);
        s_dist[warp] = d;
    }
    __syncthreads();

    __shared__ bool s_last;
    if (threadIdx.x == 0) {
        float s = 0.f;
        #pragma unroll
        for (int w = 0; w < WARPS_PER_BLOCK; ++w) s += s_dist[w];
        g_partials[blockIdx.x] = s;
        __threadfence();
        unsigned int ticket = atomicAdd(&g_count, 1u);
        s_last = (ticket == NBLOCKS - 1);
    }
    __syncthreads();

    if (s_last) {
        // Deterministic final reduction over 2048 partials (L2-resident).
        __shared__ float sm[THREADS];
        float s = 0.f;
        #pragma unroll
        for (int i = threadIdx.x; i < NBLOCKS; i += THREADS) s += g_partials[i];
        sm[threadIdx.x] = s;
        __syncthreads();
        #pragma unroll
        for (int stride = THREADS / 2; stride > 0; stride >>= 1) {
            if (threadIdx.x < stride) sm[threadIdx.x] += sm[threadIdx.x + stride];
            __syncthreads();
        }
        if (threadIdx.x == 0) {
            out[0] = sm[0] * (1.0f / (float)B_ROWS);
            g_count = 0;
        }
    }
}

extern "C" void kernel_launch(void* const* d_in, const int* in_sizes, int n_in,
                              void* d_out, int out_size)
{
    const float* x       = (const float*)d_in[0];
    const int*   labels  = (const int*)d_in[1];
    const float* centers = (const float*)d_in[2];
    float*       out     = (float*)d_out;

    cudaFuncSetAttribute(proximity_fused_kernel,
                         cudaFuncAttributeMaxDynamicSharedMemorySize, SMEM_TOTAL);
    proximity_fused_kernel<<<NBLOCKS, THREADS, SMEM_TOTAL>>>(x, labels, centers, out);
}

// round 12
// speedup vs baseline: 1.7847x; 1.7847x over previous
#include <cuda_runtime.h>
#include <cstdint>

#define B_ROWS 16384
#define NCLASS 1000
#define DIM 1024
#define ROW_BYTES (DIM * 4)            // 4096 B
#define TILE_ROWS 8
#define TILE_X_BYTES (TILE_ROWS * ROW_BYTES)   // 32768
#define STAGE_BYTES (2 * TILE_X_BYTES)         // 65536 (x slab + 8 c rows)
#define STAGES 3
#define NBLK 148
#define WARPS_PER_BLOCK 8
#define THREADS (WARPS_PER_BLOCK * 32)
#define NTILES (B_ROWS / TILE_ROWS)            // 2048
#define MAX_TILES_PER_BLOCK 14                 // ceil(2048/148)

#define SMEM_PAD 128                            // mbarriers live in [0,128)
#define SMEM_TOTAL (SMEM_PAD + STAGES * STAGE_BYTES)   // 196736

__device__ float g_partials[NBLK];
__device__ unsigned int g_count;   // zero at load; reset each run -> graph-replay safe

__device__ __forceinline__ uint32_t s2u(const void* p) {
    uint32_t a;
    asm("{ .reg .u64 t; cvta.to.shared.u64 t, %1; cvt.u32.u64 %0, t; }"
        : "=r"(a) : "l"(p));
    return a;
}
__device__ __forceinline__ void mbar_init(uint32_t m, uint32_t cnt) {
    asm volatile("mbarrier.init.shared.b64 [%0], %1;" :: "r"(m), "r"(cnt) : "memory");
}
__device__ __forceinline__ void mbar_expect_tx(uint32_t m, uint32_t bytes) {
    asm volatile("mbarrier.arrive.expect_tx.shared.b64 _, [%0], %1;"
                 :: "r"(m), "r"(bytes) : "memory");
}
__device__ __forceinline__ void bulk_g2s(uint32_t dst, const void* src,
                                         uint32_t bytes, uint32_t m) {
    asm volatile(
        "cp.async.bulk.shared::cta.global.mbarrier::complete_tx::bytes "
        "[%0], [%1], %2, [%3];"
        :: "r"(dst), "l"(src), "r"(bytes), "r"(m) : "memory");
}
__device__ __forceinline__ void mbar_wait_parity(uint32_t m, uint32_t parity) {
    asm volatile(
        "{\n\t"
        ".reg .pred P;\n\t"
        "W_%=: mbarrier.try_wait.parity.acquire.cta.shared::cta.b64 P, [%0], %1, 0x989680;\n\t"
        "@P bra D_%=;\n\t"
        "bra W_%=;\n\t"
        "D_%=:\n\t"
        "}"
        :: "r"(m), "r"(parity) : "memory");
}

// Persistent blocks, 3-stage TMA-style pipeline. Tile = 8 rows (x slab + 8
// gathered center rows) per 64KB stage buffer.
__global__ __launch_bounds__(THREADS) void proximity_pipe_kernel(
    const float* __restrict__ x,
    const int* __restrict__ labels,
    const float* __restrict__ centers,
    float* __restrict__ out)
{
    extern __shared__ char smem[];
    const uint32_t sbase = s2u(smem);

    __shared__ int   sLabels[MAX_TILES_PER_BLOCK * TILE_ROWS];
    __shared__ float s_dist[2][WARPS_PER_BLOCK];
    __shared__ bool  s_last;

    const int warp = threadIdx.x >> 5;
    const int lane = threadIdx.x & 31;
    const int b    = blockIdx.x;

    // Tiles this block owns: b, b+148, b+296, ...
    const int T = (NTILES - b + NBLK - 1) / NBLK;   // 13 or 14

    // Prolog: init mbarriers, prefetch labels for all my tiles into smem.
    if (threadIdx.x < STAGES) mbar_init(sbase + threadIdx.x * 8, 1);
    for (int k = threadIdx.x; k < T * TILE_ROWS; k += THREADS) {
        int j = k / TILE_ROWS, r = k % TILE_ROWS;
        int lab = labels[(b + NBLK * j) * TILE_ROWS + r];
        sLabels[k] = min(max(lab, 0), NCLASS - 1);
    }
    __syncthreads();

    // Fill helper (thread 0 only): stage s <- tile j.
    auto fill = [&](int s, int j) {
        const uint32_t mbar = sbase + s * 8;
        const uint32_t buf  = sbase + SMEM_PAD + s * STAGE_BYTES;
        const int tt = b + NBLK * j;
        mbar_expect_tx(mbar, STAGE_BYTES);
        bulk_g2s(buf, x + (size_t)tt * TILE_ROWS * DIM, TILE_X_BYTES, mbar);
        #pragma unroll
        for (int i = 0; i < TILE_ROWS; ++i) {
            bulk_g2s(buf + TILE_X_BYTES + i * ROW_BYTES,
                     centers + (size_t)sLabels[j * TILE_ROWS + i] * DIM,
                     ROW_BYTES, mbar);
        }
    };

    if (threadIdx.x == 0) {
        #pragma unroll
        for (int s = 0; s < STAGES; ++s)
            if (s < T) fill(s, s);
    }

    int   par[STAGES] = {0, 0, 0};
    float psum = 0.f;   // meaningful on thread 0 only

    for (int t = 0; t < T; ++t) {
        const int s = t % STAGES;
        mbar_wait_parity(sbase + s * 8, par[s]);
        par[s] ^= 1;

        const char* buf = smem + SMEM_PAD + s * STAGE_BYTES;
        const float4* __restrict__ xs =
            reinterpret_cast<const float4*>(buf + warp * ROW_BYTES);
        const float4* __restrict__ cs =
            reinterpret_cast<const float4*>(buf + TILE_X_BYTES + warp * ROW_BYTES);

        float sxx = 0.f, scc = 0.f, sxc = 0.f;
        #pragma unroll
        for (int i = 0; i < 8; ++i) {
            float4 xv = xs[lane + 32 * i];
            float4 cv = cs[lane + 32 * i];
            sxx = fmaf(xv.x, xv.x, sxx);
            sxx = fmaf(xv.y, xv.y, sxx);
            sxx = fmaf(xv.z, xv.z, sxx);
            sxx = fmaf(xv.w, xv.w, sxx);
            scc = fmaf(cv.x, cv.x, scc);
            scc = fmaf(cv.y, cv.y, scc);
            scc = fmaf(cv.z, cv.z, scc);
            scc = fmaf(cv.w, cv.w, scc);
            sxc = fmaf(xv.x, cv.x, sxc);
            sxc = fmaf(xv.y, cv.y, sxc);
            sxc = fmaf(xv.z, cv.z, sxc);
            sxc = fmaf(xv.w, cv.w, sxc);
        }
        #pragma unroll
        for (int off = 16; off > 0; off >>= 1) {
            sxx += __shfl_down_sync(0xFFFFFFFFu, sxx, off);
            scc += __shfl_down_sync(0xFFFFFFFFu, scc, off);
            sxc += __shfl_down_sync(0xFFFFFFFFu, sxc, off);
        }
        if (lane == 0) {
            const float eps = 1e-12f;
            float nx = fmaxf(sqrtf(sxx), eps);
            float nc = fmaxf(sqrtf(scc), eps);
            float d = sxx / (nx * nx) + scc / (nc * nc) - 2.0f * sxc / (nx * nc);
            d = fminf(fmaxf(d, 1e-12f), 1e12f);
            s_dist[t & 1][warp] = d;
        }
        __syncthreads();   // buffer s fully consumed; s_dist slot ready

        if (threadIdx.x == 0) {
            #pragma unroll
            for (int w = 0; w < WARPS_PER_BLOCK; ++w) psum += s_dist[t & 1][w];
            if (t + STAGES < T) fill(s, t + STAGES);
        }
    }

    if (threadIdx.x == 0) {
        g_partials[b] = psum;
        __threadfence();
        unsigned int ticket = atomicAdd(&g_count, 1u);
        s_last = (ticket == NBLK - 1);
    }
    __syncthreads();

    if (s_last) {
        // Deterministic final reduction over 148 partials.
        __shared__ float sm[THREADS];
        float s = (threadIdx.x < NBLK) ? g_partials[threadIdx.x] : 0.f;
        sm[threadIdx.x] = s;
        __syncthreads();
        #pragma unroll
        for (int stride = THREADS / 2; stride > 0; stride >>= 1) {
            if (threadIdx.x < stride) sm[threadIdx.x] += sm[threadIdx.x + stride];
            __syncthreads();
        }
        if (threadIdx.x == 0) {
            out[0] = sm[0] * (1.0f / (float)B_ROWS);
            g_count = 0;
        }
    }
}

extern "C" void kernel_launch(void* const* d_in, const int* in_sizes, int n_in,
                              void* d_out, int out_size)
{
    const float* x       = (const float*)d_in[0];
    const int*   labels  = (const int*)d_in[1];
    const float* centers = (const float*)d_in[2];
    float*       out     = (float*)d_out;

    cudaFuncSetAttribute(proximity_pipe_kernel,
                         cudaFuncAttributeMaxDynamicSharedMemorySize, SMEM_TOTAL);
    proximity_pipe_kernel<<<NBLK, THREADS, SMEM_TOTAL>>>(x, labels, centers, out);
}